// round 3
// baseline (speedup 1.0000x reference)
#include <cuda_runtime.h>
#include <math.h>

// B=8, N=1024, C=768, H=12, D=64, level=8, thresh=1.0, scale=0.125
__device__ __align__(16) signed char g_q[8 * 12 * 1024 * 64];
__device__ __align__(16) signed char g_k[8 * 12 * 1024 * 64];
__device__ __align__(16) signed char g_v[8 * 12 * 1024 * 64];
__device__ __align__(16) signed char g_t[8192 * 768];

typedef unsigned long long u64;

__device__ __forceinline__ int tern_of(float v) {
    const float u = v + 0.5f;
    return (u >= 1.0f) ? 1 : ((u < 0.0f) ? -1 : 0);
}

__device__ __forceinline__ u64 pack2(float x, float y) {
    u64 r; asm("mov.b64 %0, {%1, %2};" : "=l"(r) : "f"(x), "f"(y)); return r;
}
__device__ __forceinline__ float2 unpack2(u64 v) {
    float2 f; asm("mov.b64 {%0, %1}, %2;" : "=f"(f.x), "=f"(f.y) : "l"(v)); return f;
}
__device__ __forceinline__ void ffma2(u64& d, u64 a, u64 b) {
    asm("fma.rn.f32x2 %0, %1, %2, %0;" : "+l"(d) : "l"(a), "l"(b));
}

// ---------------------------------------------------------------------------
// GEMM1: QKV[m,o] = sum_c X[m,c]*Wqkv[o,c]  (M=8192,N=2304,K=768, fp32)
// 128x128 tile, 8x8/thread, BK=8, double-buffered, packed f32x2 FFMA.
// k-accumulation order identical to the scalar version (bit-exact results).
// ---------------------------------------------------------------------------
__global__ void __launch_bounds__(256, 2) gemm_qkv_kernel(const float* __restrict__ X,
                                                          const float* __restrict__ W) {
    __shared__ float As[2][8][132];
    __shared__ float Bs[2][8][132];
    const int tid = threadIdx.x;
    const int tx = tid & 15, ty = tid >> 4;
    const int rowBase = blockIdx.y * 128;
    const int colBase = blockIdx.x * 128;
    const int lr = tid >> 1;
    const int lk = (tid & 1) * 4;

    const float* Ag = X + (size_t)(rowBase + lr) * 768 + lk;
    const float* Bg = W + (size_t)(colBase + lr) * 768 + lk;

    u64 acc2[8][4];
#pragma unroll
    for (int i = 0; i < 8; i++)
#pragma unroll
        for (int j = 0; j < 4; j++) acc2[i][j] = 0ULL;

    {
        const float4 a4 = *(const float4*)Ag;
        const float4 b4 = *(const float4*)Bg;
        As[0][lk + 0][lr] = a4.x; As[0][lk + 1][lr] = a4.y;
        As[0][lk + 2][lr] = a4.z; As[0][lk + 3][lr] = a4.w;
        Bs[0][lk + 0][lr] = b4.x; Bs[0][lk + 1][lr] = b4.y;
        Bs[0][lk + 2][lr] = b4.z; Bs[0][lk + 3][lr] = b4.w;
    }
    __syncthreads();

    int buf = 0;
    for (int kt = 0; kt < 768; kt += 8) {
        float4 na, nb;
        const bool nxt = (kt + 8) < 768;
        if (nxt) {
            na = *(const float4*)(Ag + kt + 8);
            nb = *(const float4*)(Bg + kt + 8);
        }
#pragma unroll
        for (int kk = 0; kk < 8; kk++) {
            float a[8];
            *(float4*)(a)     = *(const float4*)&As[buf][kk][ty * 8];
            *(float4*)(a + 4) = *(const float4*)&As[buf][kk][ty * 8 + 4];
            const u64* bp = (const u64*)&Bs[buf][kk][tx * 8];
            const u64 b0 = bp[0], b1 = bp[1], b2 = bp[2], b3 = bp[3];
#pragma unroll
            for (int i = 0; i < 8; i++) {
                const u64 a2 = pack2(a[i], a[i]);
                ffma2(acc2[i][0], a2, b0);
                ffma2(acc2[i][1], a2, b1);
                ffma2(acc2[i][2], a2, b2);
                ffma2(acc2[i][3], a2, b3);
            }
        }
        if (nxt) {
            const int nb2 = buf ^ 1;
            As[nb2][lk + 0][lr] = na.x; As[nb2][lk + 1][lr] = na.y;
            As[nb2][lk + 2][lr] = na.z; As[nb2][lk + 3][lr] = na.w;
            Bs[nb2][lk + 0][lr] = nb.x; Bs[nb2][lk + 1][lr] = nb.y;
            Bs[nb2][lk + 2][lr] = nb.z; Bs[nb2][lk + 3][lr] = nb.w;
        }
        __syncthreads();
        buf ^= 1;
    }

    const int sec = colBase / 768;  // 0=q,1=k,2=v
    signed char* dst = (sec == 0) ? g_q : ((sec == 1) ? g_k : g_v);
    const int cc = colBase - sec * 768 + tx * 8;
    const int h = cc >> 6;
    const int d0 = cc & 63;
#pragma unroll
    for (int i = 0; i < 8; i++) {
        const int row = rowBase + ty * 8 + i;
        const int bb = row >> 10;
        const int nn = row & 1023;
        const float2 v0 = unpack2(acc2[i][0]);
        const float2 v1 = unpack2(acc2[i][1]);
        const float2 v2 = unpack2(acc2[i][2]);
        const float2 v3 = unpack2(acc2[i][3]);
        unsigned lo = 0, hi = 0;
        lo |= (unsigned)(tern_of(v0.x) & 0xFF);
        lo |= ((unsigned)(tern_of(v0.y) & 0xFF)) << 8;
        lo |= ((unsigned)(tern_of(v1.x) & 0xFF)) << 16;
        lo |= ((unsigned)(tern_of(v1.y) & 0xFF)) << 24;
        hi |= (unsigned)(tern_of(v2.x) & 0xFF);
        hi |= ((unsigned)(tern_of(v2.y) & 0xFF)) << 8;
        hi |= ((unsigned)(tern_of(v3.x) & 0xFF)) << 16;
        hi |= ((unsigned)(tern_of(v3.y) & 0xFF)) << 24;
        uint2* p = (uint2*)(dst + ((size_t)((bb * 12 + h) * 1024 + nn) * 64 + d0));
        *p = make_uint2(lo, hi);
    }
}

// ---------------------------------------------------------------------------
// Attention. Only the argmax logit can spike (non-max p <= e^-0.125/(1+e^-0.125)
// < 0.5); spike iff 1/Z >= 0.5. exp values come from a 129-entry table of
// expf(0.125*d) — bit-identical to per-element expf of the passing version.
// Logits are kept in registers (each lane re-reads only its own m's).
// ---------------------------------------------------------------------------
__global__ void __launch_bounds__(256, 2) attn_kernel() {
    extern __shared__ int smem_dyn[];
    int* Kp = smem_dyn;                          // [16][1024] int32 = 64KB
    float* table = (float*)(smem_dyn + 16384);   // 129 floats

    const int bh = blockIdx.x;
    const int bb = bh / 12, h = bh % 12;
    const int tid = threadIdx.x;
    const int lane = tid & 31, warp = tid >> 5;

    const signed char* kbase = g_k + (size_t)bh * 65536;
    const signed char* vbase = g_v + (size_t)bh * 65536;
    const signed char* qbase = g_q + (size_t)bh * 65536;

    if (tid < 129) table[tid] = expf(0.125f * (float)(tid - 128));

    for (int flat = tid; flat < 4096; flat += 256) {
        const int m = flat >> 2, wg = flat & 3;
        const int4 kv = *(const int4*)(kbase + m * 64 + wg * 16);
        Kp[(wg * 4 + 0) * 1024 + m] = kv.x;
        Kp[(wg * 4 + 1) * 1024 + m] = kv.y;
        Kp[(wg * 4 + 2) * 1024 + m] = kv.z;
        Kp[(wg * 4 + 3) * 1024 + m] = kv.w;
    }
    __syncthreads();

    const int rowBase = blockIdx.y * 64;

#pragma unroll 1
    for (int pass = 0; pass < 4; pass++) {
        const int r0 = rowBase + pass * 16 + warp * 2;
        const int r1 = r0 + 1;

        int q0[16], q1[16];
        {
            const int4* qp = (const int4*)(qbase + (size_t)r0 * 64);
#pragma unroll
            for (int w = 0; w < 4; w++) {
                const int4 t0 = qp[w];
                q0[w * 4 + 0] = t0.x; q0[w * 4 + 1] = t0.y;
                q0[w * 4 + 2] = t0.z; q0[w * 4 + 3] = t0.w;
                const int4 t1 = qp[4 + w];
                q1[w * 4 + 0] = t1.x; q1[w * 4 + 1] = t1.y;
                q1[w * 4 + 2] = t1.z; q1[w * 4 + 3] = t1.w;
            }
        }

        // Pass 1: dp4a logits (ints in [-64,64]), packed two rows per register.
        int av[32];
        int amax0 = -1000, amax1 = -1000;
#pragma unroll
        for (int k = 0; k < 32; k++) {
            const int m = lane + 32 * k;
            int a0 = 0, a1 = 0;
#pragma unroll
            for (int w = 0; w < 16; w++) {
                const int kv = Kp[w * 1024 + m];
                a0 = __dp4a(q0[w], kv, a0);
                a1 = __dp4a(q1[w], kv, a1);
            }
            av[k] = (a0 & 0xFFFF) | (a1 << 16);
            amax0 = max(amax0, a0);
            amax1 = max(amax1, a1);
        }
#pragma unroll
        for (int off = 16; off; off >>= 1) {
            amax0 = max(amax0, __shfl_xor_sync(0xffffffffu, amax0, off));
            amax1 = max(amax1, __shfl_xor_sync(0xffffffffu, amax1, off));
        }

        // Pass 2: Z via exp table (same per-lane m-order + shfl tree as before)
        float Z0 = 0.0f, Z1 = 0.0f;
        int pos0 = -1, pos1 = -1;
#pragma unroll
        for (int k = 0; k < 32; k++) {
            const int a0 = (av[k] << 16) >> 16;
            const int a1 = av[k] >> 16;
            Z0 += table[a0 - amax0 + 128];
            Z1 += table[a1 - amax1 + 128];
            if (a0 == amax0) pos0 = lane + 32 * k;
            if (a1 == amax1) pos1 = lane + 32 * k;
        }
#pragma unroll
        for (int off = 16; off; off >>= 1) {
            Z0 += __shfl_xor_sync(0xffffffffu, Z0, off);
            Z1 += __shfl_xor_sync(0xffffffffu, Z1, off);
        }

        const unsigned bal0 = __ballot_sync(0xffffffffu, pos0 >= 0);
        const unsigned bal1 = __ballot_sync(0xffffffffu, pos1 >= 0);
        const int mpos0 = __shfl_sync(0xffffffffu, pos0, __ffs(bal0) - 1);
        const int mpos1 = __shfl_sync(0xffffffffu, pos1, __ffs(bal1) - 1);

        const float p0 = 1.0f / Z0;
        const float p1 = 1.0f / Z1;
        const bool s0 = (p0 + 0.5f) >= 1.0f;
        const bool s1 = (p1 + 0.5f) >= 1.0f;

        char2 o0 = make_char2(0, 0), o1 = make_char2(0, 0);
        if (s0) o0 = *(const char2*)(vbase + (size_t)mpos0 * 64 + 2 * lane);
        if (s1) o1 = *(const char2*)(vbase + (size_t)mpos1 * 64 + 2 * lane);
        // V values are already ternary; tern(v)=v. No spike -> 0.
        *(char2*)(g_t + (size_t)(bb * 1024 + r0) * 768 + h * 64 + 2 * lane) = o0;
        *(char2*)(g_t + (size_t)(bb * 1024 + r1) * 768 + h * 64 + 2 * lane) = o1;
    }
}

// ---------------------------------------------------------------------------
// GEMM2: Out[m,o] = tern( sum_c T[m,c]*Wproj[o,c] )  (M=8192,N=768,K=768)
// ---------------------------------------------------------------------------
__global__ void __launch_bounds__(256, 2) gemm_proj_kernel(const float* __restrict__ W,
                                                           float* __restrict__ Out) {
    __shared__ float As[2][8][132];
    __shared__ float Bs[2][8][132];
    const int tid = threadIdx.x;
    const int tx = tid & 15, ty = tid >> 4;
    const int rowBase = blockIdx.y * 128;
    const int colBase = blockIdx.x * 128;
    const int lr = tid >> 1;
    const int lk = (tid & 1) * 4;

    const float* Bg = W + (size_t)(colBase + lr) * 768 + lk;
    const signed char* Agc = g_t + (size_t)(rowBase + (tid & 127)) * 768;

    u64 acc2[8][4];
#pragma unroll
    for (int i = 0; i < 8; i++)
#pragma unroll
        for (int j = 0; j < 4; j++) acc2[i][j] = 0ULL;

    if (tid < 128) {
        const int2 raw = *(const int2*)(Agc);
        const signed char* cp = (const signed char*)&raw;
#pragma unroll
        for (int k2 = 0; k2 < 8; k2++) As[0][k2][tid] = (float)cp[k2];
    }
    {
        const float4 b4 = *(const float4*)Bg;
        Bs[0][lk + 0][lr] = b4.x; Bs[0][lk + 1][lr] = b4.y;
        Bs[0][lk + 2][lr] = b4.z; Bs[0][lk + 3][lr] = b4.w;
    }
    __syncthreads();

    int buf = 0;
    for (int kt = 0; kt < 768; kt += 8) {
        int2 nraw; float4 nb;
        const bool nxt = (kt + 8) < 768;
        if (nxt) {
            if (tid < 128) nraw = *(const int2*)(Agc + kt + 8);
            nb = *(const float4*)(Bg + kt + 8);
        }
#pragma unroll
        for (int kk = 0; kk < 8; kk++) {
            float a[8];
            *(float4*)(a)     = *(const float4*)&As[buf][kk][ty * 8];
            *(float4*)(a + 4) = *(const float4*)&As[buf][kk][ty * 8 + 4];
            const u64* bp = (const u64*)&Bs[buf][kk][tx * 8];
            const u64 b0 = bp[0], b1 = bp[1], b2 = bp[2], b3 = bp[3];
#pragma unroll
            for (int i = 0; i < 8; i++) {
                const u64 a2 = pack2(a[i], a[i]);
                ffma2(acc2[i][0], a2, b0);
                ffma2(acc2[i][1], a2, b1);
                ffma2(acc2[i][2], a2, b2);
                ffma2(acc2[i][3], a2, b3);
            }
        }
        if (nxt) {
            const int nb2 = buf ^ 1;
            if (tid < 128) {
                const signed char* cp = (const signed char*)&nraw;
#pragma unroll
                for (int k2 = 0; k2 < 8; k2++) As[nb2][k2][tid] = (float)cp[k2];
            }
            Bs[nb2][lk + 0][lr] = nb.x; Bs[nb2][lk + 1][lr] = nb.y;
            Bs[nb2][lk + 2][lr] = nb.z; Bs[nb2][lk + 3][lr] = nb.w;
        }
        __syncthreads();
        buf ^= 1;
    }

#pragma unroll
    for (int i = 0; i < 8; i++) {
        const int row = rowBase + ty * 8 + i;
        float o[8];
        const float2 v0 = unpack2(acc2[i][0]);
        const float2 v1 = unpack2(acc2[i][1]);
        const float2 v2 = unpack2(acc2[i][2]);
        const float2 v3 = unpack2(acc2[i][3]);
        o[0] = (float)tern_of(v0.x); o[1] = (float)tern_of(v0.y);
        o[2] = (float)tern_of(v1.x); o[3] = (float)tern_of(v1.y);
        o[4] = (float)tern_of(v2.x); o[5] = (float)tern_of(v2.y);
        o[6] = (float)tern_of(v3.x); o[7] = (float)tern_of(v3.y);
        float* op = Out + (size_t)row * 768 + colBase + tx * 8;
        *(float4*)op       = make_float4(o[0], o[1], o[2], o[3]);
        *(float4*)(op + 4) = make_float4(o[4], o[5], o[6], o[7]);
    }
}

// ---------------------------------------------------------------------------
extern "C" void kernel_launch(void* const* d_in, const int* in_sizes, int n_in,
                              void* d_out, int out_size) {
    (void)in_sizes; (void)n_in; (void)out_size;
    const float* x      = (const float*)d_in[0];
    const float* w_qkv  = (const float*)d_in[1];
    const float* w_proj = (const float*)d_in[2];
    float* out = (float*)d_out;

    cudaFuncSetAttribute(attn_kernel, cudaFuncAttributeMaxDynamicSharedMemorySize, 66560);

    gemm_qkv_kernel<<<dim3(18, 64), 256>>>(x, w_qkv);
    attn_kernel<<<dim3(96, 16), 256, 66560>>>();
    gemm_proj_kernel<<<dim3(6, 64), 256>>>(w_proj, out);
}

// round 6
// speedup vs baseline: 1.6542x; 1.6542x over previous
#include <cuda_runtime.h>
#include <math.h>

// B=8, N=1024, C=768, H=12, D=64, level=8, thresh=1.0, scale=0.125
__device__ __align__(16) signed char g_q[8 * 12 * 1024 * 64];
__device__ __align__(16) signed char g_k[8 * 12 * 1024 * 64];
__device__ __align__(16) signed char g_v[8 * 12 * 1024 * 64];
__device__ __align__(16) signed char g_t[8192 * 768];

__device__ __forceinline__ int tern_of(float v) {
    const float u = v + 0.5f;
    return (u >= 1.0f) ? 1 : ((u < 0.0f) ? -1 : 0);
}

// ---------------------------------------------------------------------------
// GEMM1: QKV[m,o] = sum_c X[m,c]*Wqkv[o,c]  (M=8192,N=2304,K=768, fp32)
// 128x128 tile, 8x8/thread, BK=16, double-buffered, scalar FFMA.
// k order strictly sequential per accumulator -> bit-identical across BK.
// ---------------------------------------------------------------------------
__global__ void __launch_bounds__(256, 2) gemm_qkv_kernel(const float* __restrict__ X,
                                                          const float* __restrict__ W) {
    __shared__ float As[2][16][132];
    __shared__ float Bs[2][16][132];
    const int tid = threadIdx.x;
    const int tx = tid & 15, ty = tid >> 4;
    const int rowBase = blockIdx.y * 128;
    const int colBase = blockIdx.x * 128;
    const int lr = tid >> 1;          // 0..127
    const int lk = (tid & 1) * 8;     // 0 or 8

    const float* Ag = X + (size_t)(rowBase + lr) * 768 + lk;
    const float* Bg = W + (size_t)(colBase + lr) * 768 + lk;

    float acc[8][8];
#pragma unroll
    for (int i = 0; i < 8; i++)
#pragma unroll
        for (int j = 0; j < 8; j++) acc[i][j] = 0.0f;

    {
        const float4 a0 = *(const float4*)Ag;
        const float4 a1 = *(const float4*)(Ag + 4);
        const float4 b0 = *(const float4*)Bg;
        const float4 b1 = *(const float4*)(Bg + 4);
        As[0][lk + 0][lr] = a0.x; As[0][lk + 1][lr] = a0.y;
        As[0][lk + 2][lr] = a0.z; As[0][lk + 3][lr] = a0.w;
        As[0][lk + 4][lr] = a1.x; As[0][lk + 5][lr] = a1.y;
        As[0][lk + 6][lr] = a1.z; As[0][lk + 7][lr] = a1.w;
        Bs[0][lk + 0][lr] = b0.x; Bs[0][lk + 1][lr] = b0.y;
        Bs[0][lk + 2][lr] = b0.z; Bs[0][lk + 3][lr] = b0.w;
        Bs[0][lk + 4][lr] = b1.x; Bs[0][lk + 5][lr] = b1.y;
        Bs[0][lk + 6][lr] = b1.z; Bs[0][lk + 7][lr] = b1.w;
    }
    __syncthreads();

    int buf = 0;
    for (int kt = 0; kt < 768; kt += 16) {
        float4 na0, na1, nb0, nb1;
        const bool nxt = (kt + 16) < 768;
        if (nxt) {
            na0 = *(const float4*)(Ag + kt + 16);
            na1 = *(const float4*)(Ag + kt + 20);
            nb0 = *(const float4*)(Bg + kt + 16);
            nb1 = *(const float4*)(Bg + kt + 20);
        }
#pragma unroll
        for (int kk = 0; kk < 16; kk++) {
            float a[8], b[8];
            *(float4*)(a)     = *(const float4*)&As[buf][kk][ty * 8];
            *(float4*)(a + 4) = *(const float4*)&As[buf][kk][ty * 8 + 4];
            *(float4*)(b)     = *(const float4*)&Bs[buf][kk][tx * 8];
            *(float4*)(b + 4) = *(const float4*)&Bs[buf][kk][tx * 8 + 4];
#pragma unroll
            for (int i = 0; i < 8; i++)
#pragma unroll
                for (int j = 0; j < 8; j++) acc[i][j] = fmaf(a[i], b[j], acc[i][j]);
        }
        if (nxt) {
            const int nb2 = buf ^ 1;
            As[nb2][lk + 0][lr] = na0.x; As[nb2][lk + 1][lr] = na0.y;
            As[nb2][lk + 2][lr] = na0.z; As[nb2][lk + 3][lr] = na0.w;
            As[nb2][lk + 4][lr] = na1.x; As[nb2][lk + 5][lr] = na1.y;
            As[nb2][lk + 6][lr] = na1.z; As[nb2][lk + 7][lr] = na1.w;
            Bs[nb2][lk + 0][lr] = nb0.x; Bs[nb2][lk + 1][lr] = nb0.y;
            Bs[nb2][lk + 2][lr] = nb0.z; Bs[nb2][lk + 3][lr] = nb0.w;
            Bs[nb2][lk + 4][lr] = nb1.x; Bs[nb2][lk + 5][lr] = nb1.y;
            Bs[nb2][lk + 6][lr] = nb1.z; Bs[nb2][lk + 7][lr] = nb1.w;
        }
        __syncthreads();
        buf ^= 1;
    }

    const int sec = colBase / 768;  // 0=q,1=k,2=v
    signed char* dst = (sec == 0) ? g_q : ((sec == 1) ? g_k : g_v);
    const int cc = colBase - sec * 768 + tx * 8;
    const int h = cc >> 6;
    const int d0 = cc & 63;
#pragma unroll
    for (int i = 0; i < 8; i++) {
        const int row = rowBase + ty * 8 + i;
        const int bb = row >> 10;
        const int nn = row & 1023;
        unsigned lo = 0, hi = 0;
#pragma unroll
        for (int j = 0; j < 4; j++) {
            lo |= ((unsigned)(tern_of(acc[i][j])     & 0xFF)) << (8 * j);
            hi |= ((unsigned)(tern_of(acc[i][j + 4]) & 0xFF)) << (8 * j);
        }
        uint2* p = (uint2*)(dst + ((size_t)((bb * 12 + h) * 1024 + nn) * 64 + d0));
        *p = make_uint2(lo, hi);
    }
}

// ---------------------------------------------------------------------------
// Attention. Only the argmax logit can spike (non-max p <= e^-0.125/(1+e^-0.125)
// < 0.5); spike iff 1/Z >= 0.5. exp values from a 129-entry table of
// expf(0.125*d) — bit-identical to per-element expf. Logits stay in registers.
// ---------------------------------------------------------------------------
__global__ void __launch_bounds__(256, 2) attn_kernel() {
    extern __shared__ int smem_dyn[];
    int* Kp = smem_dyn;                          // [16][1024] int32 = 64KB
    float* table = (float*)(smem_dyn + 16384);   // 129 floats

    const int bh = blockIdx.x;
    const int bb = bh / 12, h = bh % 12;
    const int tid = threadIdx.x;
    const int lane = tid & 31, warp = tid >> 5;

    const signed char* kbase = g_k + (size_t)bh * 65536;
    const signed char* vbase = g_v + (size_t)bh * 65536;
    const signed char* qbase = g_q + (size_t)bh * 65536;

    if (tid < 129) table[tid] = expf(0.125f * (float)(tid - 128));

    for (int flat = tid; flat < 4096; flat += 256) {
        const int m = flat >> 2, wg = flat & 3;
        const int4 kv = *(const int4*)(kbase + m * 64 + wg * 16);
        Kp[(wg * 4 + 0) * 1024 + m] = kv.x;
        Kp[(wg * 4 + 1) * 1024 + m] = kv.y;
        Kp[(wg * 4 + 2) * 1024 + m] = kv.z;
        Kp[(wg * 4 + 3) * 1024 + m] = kv.w;
    }
    __syncthreads();

    const int rowBase = blockIdx.y * 64;

#pragma unroll 1
    for (int pass = 0; pass < 4; pass++) {
        const int r0 = rowBase + pass * 16 + warp * 2;
        const int r1 = r0 + 1;

        int q0[16], q1[16];
        {
            const int4* qp = (const int4*)(qbase + (size_t)r0 * 64);
#pragma unroll
            for (int w = 0; w < 4; w++) {
                const int4 t0 = qp[w];
                q0[w * 4 + 0] = t0.x; q0[w * 4 + 1] = t0.y;
                q0[w * 4 + 2] = t0.z; q0[w * 4 + 3] = t0.w;
                const int4 t1 = qp[4 + w];
                q1[w * 4 + 0] = t1.x; q1[w * 4 + 1] = t1.y;
                q1[w * 4 + 2] = t1.z; q1[w * 4 + 3] = t1.w;
            }
        }

        // Pass 1: dp4a logits (ints in [-64,64]), two rows packed per register.
        int av[32];
        int amax0 = -1000, amax1 = -1000;
#pragma unroll
        for (int k = 0; k < 32; k++) {
            const int m = lane + 32 * k;
            int a0 = 0, a1 = 0;
#pragma unroll
            for (int w = 0; w < 16; w++) {
                const int kv = Kp[w * 1024 + m];
                a0 = __dp4a(q0[w], kv, a0);
                a1 = __dp4a(q1[w], kv, a1);
            }
            av[k] = (a0 & 0xFFFF) | (a1 << 16);
            amax0 = max(amax0, a0);
            amax1 = max(amax1, a1);
        }
#pragma unroll
        for (int off = 16; off; off >>= 1) {
            amax0 = max(amax0, __shfl_xor_sync(0xffffffffu, amax0, off));
            amax1 = max(amax1, __shfl_xor_sync(0xffffffffu, amax1, off));
        }

        // Pass 2: Z via exp table (same per-lane m order + shfl tree)
        float Z0 = 0.0f, Z1 = 0.0f;
        int pos0 = -1, pos1 = -1;
#pragma unroll
        for (int k = 0; k < 32; k++) {
            const int a0 = (av[k] << 16) >> 16;
            const int a1 = av[k] >> 16;
            Z0 += table[a0 - amax0 + 128];
            Z1 += table[a1 - amax1 + 128];
            if (a0 == amax0) pos0 = lane + 32 * k;
            if (a1 == amax1) pos1 = lane + 32 * k;
        }
#pragma unroll
        for (int off = 16; off; off >>= 1) {
            Z0 += __shfl_xor_sync(0xffffffffu, Z0, off);
            Z1 += __shfl_xor_sync(0xffffffffu, Z1, off);
        }

        const unsigned bal0 = __ballot_sync(0xffffffffu, pos0 >= 0);
        const unsigned bal1 = __ballot_sync(0xffffffffu, pos1 >= 0);
        const int mpos0 = __shfl_sync(0xffffffffu, pos0, __ffs(bal0) - 1);
        const int mpos1 = __shfl_sync(0xffffffffu, pos1, __ffs(bal1) - 1);

        const float p0 = 1.0f / Z0;
        const float p1 = 1.0f / Z1;
        const bool s0 = (p0 + 0.5f) >= 1.0f;
        const bool s1 = (p1 + 0.5f) >= 1.0f;

        char2 o0 = make_char2(0, 0), o1 = make_char2(0, 0);
        if (s0) o0 = *(const char2*)(vbase + (size_t)mpos0 * 64 + 2 * lane);
        if (s1) o1 = *(const char2*)(vbase + (size_t)mpos1 * 64 + 2 * lane);
        // V already ternary: tern(v)=v. No spike -> 0.
        *(char2*)(g_t + (size_t)(bb * 1024 + r0) * 768 + h * 64 + 2 * lane) = o0;
        *(char2*)(g_t + (size_t)(bb * 1024 + r1) * 768 + h * 64 + 2 * lane) = o1;
    }
}

// ---------------------------------------------------------------------------
// GEMM2: Out[m,o] = tern( sum_c T[m,c]*Wproj[o,c] )  (M=8192,N=768,K=768)
// T ternary int8, W fp32. 128x128 tile, BK=16, scalar FFMA.
// ---------------------------------------------------------------------------
__global__ void __launch_bounds__(256, 2) gemm_proj_kernel(const float* __restrict__ W,
                                                           float* __restrict__ Out) {
    __shared__ float As[2][16][132];
    __shared__ float Bs[2][16][132];
    const int tid = threadIdx.x;
    const int tx = tid & 15, ty = tid >> 4;
    const int rowBase = blockIdx.y * 128;
    const int colBase = blockIdx.x * 128;
    const int lr = tid >> 1;
    const int lk = (tid & 1) * 8;

    const float* Bg = W + (size_t)(colBase + lr) * 768 + lk;
    const signed char* Agc = g_t + (size_t)(rowBase + (tid & 127)) * 768;

    float acc[8][8];
#pragma unroll
    for (int i = 0; i < 8; i++)
#pragma unroll
        for (int j = 0; j < 8; j++) acc[i][j] = 0.0f;

    if (tid < 128) {
        const int4 raw = *(const int4*)(Agc);
        const signed char* cp = (const signed char*)&raw;
#pragma unroll
        for (int k2 = 0; k2 < 16; k2++) As[0][k2][tid] = (float)cp[k2];
    }
    {
        const float4 b0 = *(const float4*)Bg;
        const float4 b1 = *(const float4*)(Bg + 4);
        Bs[0][lk + 0][lr] = b0.x; Bs[0][lk + 1][lr] = b0.y;
        Bs[0][lk + 2][lr] = b0.z; Bs[0][lk + 3][lr] = b0.w;
        Bs[0][lk + 4][lr] = b1.x; Bs[0][lk + 5][lr] = b1.y;
        Bs[0][lk + 6][lr] = b1.z; Bs[0][lk + 7][lr] = b1.w;
    }
    __syncthreads();

    int buf = 0;
    for (int kt = 0; kt < 768; kt += 16) {
        int4 nraw; float4 nb0, nb1;
        const bool nxt = (kt + 16) < 768;
        if (nxt) {
            if (tid < 128) nraw = *(const int4*)(Agc + kt + 16);
            nb0 = *(const float4*)(Bg + kt + 16);
            nb1 = *(const float4*)(Bg + kt + 20);
        }
#pragma unroll
        for (int kk = 0; kk < 16; kk++) {
            float a[8], b[8];
            *(float4*)(a)     = *(const float4*)&As[buf][kk][ty * 8];
            *(float4*)(a + 4) = *(const float4*)&As[buf][kk][ty * 8 + 4];
            *(float4*)(b)     = *(const float4*)&Bs[buf][kk][tx * 8];
            *(float4*)(b + 4) = *(const float4*)&Bs[buf][kk][tx * 8 + 4];
#pragma unroll
            for (int i = 0; i < 8; i++)
#pragma unroll
                for (int j = 0; j < 8; j++) acc[i][j] = fmaf(a[i], b[j], acc[i][j]);
        }
        if (nxt) {
            const int nb2 = buf ^ 1;
            if (tid < 128) {
                const signed char* cp = (const signed char*)&nraw;
#pragma unroll
                for (int k2 = 0; k2 < 16; k2++) As[nb2][k2][tid] = (float)cp[k2];
            }
            Bs[nb2][lk + 0][lr] = nb0.x; Bs[nb2][lk + 1][lr] = nb0.y;
            Bs[nb2][lk + 2][lr] = nb0.z; Bs[nb2][lk + 3][lr] = nb0.w;
            Bs[nb2][lk + 4][lr] = nb1.x; Bs[nb2][lk + 5][lr] = nb1.y;
            Bs[nb2][lk + 6][lr] = nb1.z; Bs[nb2][lk + 7][lr] = nb1.w;
        }
        __syncthreads();
        buf ^= 1;
    }

#pragma unroll
    for (int i = 0; i < 8; i++) {
        const int row = rowBase + ty * 8 + i;
        float o[8];
#pragma unroll
        for (int j = 0; j < 8; j++) {
            const float u = acc[i][j] + 0.5f;
            o[j] = (u >= 1.0f) ? 1.0f : ((u < 0.0f) ? -1.0f : 0.0f);
        }
        float* op = Out + (size_t)row * 768 + colBase + tx * 8;
        *(float4*)op       = make_float4(o[0], o[1], o[2], o[3]);
        *(float4*)(op + 4) = make_float4(o[4], o[5], o[6], o[7]);
    }
}

// ---------------------------------------------------------------------------
extern "C" void kernel_launch(void* const* d_in, const int* in_sizes, int n_in,
                              void* d_out, int out_size) {
    (void)in_sizes; (void)n_in; (void)out_size;
    const float* x      = (const float*)d_in[0];
    const float* w_qkv  = (const float*)d_in[1];
    const float* w_proj = (const float*)d_in[2];
    float* out = (float*)d_out;

    cudaFuncSetAttribute(attn_kernel, cudaFuncAttributeMaxDynamicSharedMemorySize, 66560);

    gemm_qkv_kernel<<<dim3(18, 64), 256>>>(x, w_qkv);
    attn_kernel<<<dim3(96, 16), 256, 66560>>>();
    gemm_proj_kernel<<<dim3(6, 64), 256>>>(w_proj, out);
}

// round 7
// speedup vs baseline: 2.5692x; 1.5531x over previous
#include <cuda_runtime.h>
#include <math.h>

// B=8, N=1024, C=768, H=12, D=64, level=8, thresh=1.0, scale=0.125
__device__ __align__(16) signed char g_q[8 * 12 * 1024 * 64];
__device__ __align__(16) signed char g_k[8 * 12 * 1024 * 64];
__device__ __align__(16) signed char g_v[8 * 12 * 1024 * 64];
__device__ __align__(16) signed char g_t[8192 * 768];
__device__ int g_flag[64];   // per-128-row-group: any attention spike?

__device__ __forceinline__ int tern_of(float v) {
    const float u = v + 0.5f;
    return (u >= 1.0f) ? 1 : ((u < 0.0f) ? -1 : 0);
}

// ---------------------------------------------------------------------------
// GEMM1: QKV[m,o] = sum_c X[m,c]*Wqkv[o,c]  (M=8192, N=2304, K=768, fp32)
// 128x256 block tile, 8x16 per thread (as 4 groups of 4 cols at 64 stride),
// BK=16, double-buffered dynamic smem, scalar FFMA, k-order bit-exact.
// ---------------------------------------------------------------------------
#define AS(b, k, r) As[((b) * 16 + (k)) * 132 + (r)]
#define BS(b, k, c) Bs[((b) * 16 + (k)) * 260 + (c)]

__global__ void __launch_bounds__(256, 1) gemm_qkv_kernel(const float* __restrict__ X,
                                                          const float* __restrict__ W) {
    extern __shared__ float smem_f[];
    float* As = smem_f;                 // [2][16][132]
    float* Bs = smem_f + 2 * 16 * 132;  // [2][16][260]

    const int tid = threadIdx.x;
    const int tx = tid & 15, ty = tid >> 4;     // micro-tile coords
    const int rowBase = blockIdx.y * 128;
    const int colBase = blockIdx.x * 256;

    // staging coords: thread loads 64B (float4) rows
    const int sr = tid >> 2;            // 0..63
    const int sc = (tid & 3) * 4;       // 0,4,8,12

    const float* Ag0 = X + (size_t)(rowBase + sr) * 768 + sc;
    const float* Ag1 = Ag0 + (size_t)64 * 768;
    const float* Bg0 = W + (size_t)(colBase + sr) * 768 + sc;

    float acc[8][16];
#pragma unroll
    for (int i = 0; i < 8; i++)
#pragma unroll
        for (int j = 0; j < 16; j++) acc[i][j] = 0.0f;

    // prologue stage kt=0
    {
        const float4 a0 = *(const float4*)Ag0;
        const float4 a1 = *(const float4*)Ag1;
#pragma unroll
        for (int j = 0; j < 4; j++) {
            AS(0, sc + j, sr)      = ((const float*)&a0)[j];
            AS(0, sc + j, sr + 64) = ((const float*)&a1)[j];
        }
#pragma unroll
        for (int g = 0; g < 4; g++) {
            const float4 b = *(const float4*)(Bg0 + (size_t)(64 * g) * 768);
#pragma unroll
            for (int j = 0; j < 4; j++) BS(0, sc + j, sr + 64 * g) = ((const float*)&b)[j];
        }
    }
    __syncthreads();

    int buf = 0;
    for (int kt = 0; kt < 768; kt += 16) {
        float4 na0, na1, nb[4];
        const bool nxt = (kt + 16) < 768;
        if (nxt) {
            na0 = *(const float4*)(Ag0 + kt + 16);
            na1 = *(const float4*)(Ag1 + kt + 16);
#pragma unroll
            for (int g = 0; g < 4; g++)
                nb[g] = *(const float4*)(Bg0 + (size_t)(64 * g) * 768 + kt + 16);
        }
#pragma unroll
        for (int kk = 0; kk < 16; kk++) {
            float a[8], b[16];
            *(float4*)(a)     = *(const float4*)&AS(buf, kk, ty * 8);
            *(float4*)(a + 4) = *(const float4*)&AS(buf, kk, ty * 8 + 4);
#pragma unroll
            for (int s = 0; s < 4; s++)
                *(float4*)(b + 4 * s) = *(const float4*)&BS(buf, kk, tx * 4 + 64 * s);
#pragma unroll
            for (int i = 0; i < 8; i++)
#pragma unroll
                for (int j = 0; j < 16; j++) acc[i][j] = fmaf(a[i], b[j], acc[i][j]);
        }
        if (nxt) {
            const int nb2 = buf ^ 1;
#pragma unroll
            for (int j = 0; j < 4; j++) {
                AS(nb2, sc + j, sr)      = ((const float*)&na0)[j];
                AS(nb2, sc + j, sr + 64) = ((const float*)&na1)[j];
            }
#pragma unroll
            for (int g = 0; g < 4; g++)
#pragma unroll
                for (int j = 0; j < 4; j++)
                    BS(nb2, sc + j, sr + 64 * g) = ((const float*)&nb[g])[j];
        }
        __syncthreads();
        buf ^= 1;
    }

    // Epilogue: colBase multiple of 256; section = colBase/768.
    // Thread cols: colSec + tx*4 + 64*s  (4 contiguous cols per group, one head).
    const int sec = colBase / 768;  // 0=q,1=k,2=v
    signed char* dst = (sec == 0) ? g_q : ((sec == 1) ? g_k : g_v);
    const int colSec = colBase - sec * 768;
#pragma unroll
    for (int i = 0; i < 8; i++) {
        const int row = rowBase + ty * 8 + i;
        const int bb = row >> 10;
        const int nn = row & 1023;
#pragma unroll
        for (int s = 0; s < 4; s++) {
            const int cc = colSec + 64 * s;    // head-aligned group base
            const int h = cc >> 6;
            unsigned w = 0;
#pragma unroll
            for (int j = 0; j < 4; j++)
                w |= ((unsigned)(tern_of(acc[i][4 * s + j]) & 0xFF)) << (8 * j);
            *(unsigned*)(dst + ((size_t)((bb * 12 + h) * 1024 + nn) * 64 + tx * 4)) = w;
        }
    }
}

// ---------------------------------------------------------------------------
__global__ void init_flags_kernel() {
    if (threadIdx.x < 64) g_flag[threadIdx.x] = 0;
}

// ---------------------------------------------------------------------------
// Attention. Only the argmax logit can spike; spike iff 1/Z >= 0.5.
// exp via 129-entry table of expf(0.125*d) — bit-identical to per-element expf.
// ---------------------------------------------------------------------------
__global__ void __launch_bounds__(256, 2) attn_kernel() {
    extern __shared__ int smem_dyn[];
    int* Kp = smem_dyn;                          // [16][1024] int32 = 64KB
    float* table = (float*)(smem_dyn + 16384);   // 129 floats

    const int bh = blockIdx.x;
    const int bb = bh / 12, h = bh % 12;
    const int tid = threadIdx.x;
    const int lane = tid & 31, warp = tid >> 5;

    const signed char* kbase = g_k + (size_t)bh * 65536;
    const signed char* vbase = g_v + (size_t)bh * 65536;
    const signed char* qbase = g_q + (size_t)bh * 65536;

    if (tid < 129) table[tid] = expf(0.125f * (float)(tid - 128));

    for (int flat = tid; flat < 4096; flat += 256) {
        const int m = flat >> 2, wg = flat & 3;
        const int4 kv = *(const int4*)(kbase + m * 64 + wg * 16);
        Kp[(wg * 4 + 0) * 1024 + m] = kv.x;
        Kp[(wg * 4 + 1) * 1024 + m] = kv.y;
        Kp[(wg * 4 + 2) * 1024 + m] = kv.z;
        Kp[(wg * 4 + 3) * 1024 + m] = kv.w;
    }
    __syncthreads();

    const int rowBase = blockIdx.y * 64;

#pragma unroll 1
    for (int pass = 0; pass < 4; pass++) {
        const int r0 = rowBase + pass * 16 + warp * 2;
        const int r1 = r0 + 1;

        int q0[16], q1[16];
        {
            const int4* qp = (const int4*)(qbase + (size_t)r0 * 64);
#pragma unroll
            for (int w = 0; w < 4; w++) {
                const int4 t0 = qp[w];
                q0[w * 4 + 0] = t0.x; q0[w * 4 + 1] = t0.y;
                q0[w * 4 + 2] = t0.z; q0[w * 4 + 3] = t0.w;
                const int4 t1 = qp[4 + w];
                q1[w * 4 + 0] = t1.x; q1[w * 4 + 1] = t1.y;
                q1[w * 4 + 2] = t1.z; q1[w * 4 + 3] = t1.w;
            }
        }

        int av[32];
        int amax0 = -1000, amax1 = -1000;
#pragma unroll
        for (int k = 0; k < 32; k++) {
            const int m = lane + 32 * k;
            int a0 = 0, a1 = 0;
#pragma unroll
            for (int w = 0; w < 16; w++) {
                const int kv = Kp[w * 1024 + m];
                a0 = __dp4a(q0[w], kv, a0);
                a1 = __dp4a(q1[w], kv, a1);
            }
            av[k] = (a0 & 0xFFFF) | (a1 << 16);
            amax0 = max(amax0, a0);
            amax1 = max(amax1, a1);
        }
#pragma unroll
        for (int off = 16; off; off >>= 1) {
            amax0 = max(amax0, __shfl_xor_sync(0xffffffffu, amax0, off));
            amax1 = max(amax1, __shfl_xor_sync(0xffffffffu, amax1, off));
        }

        float Z0 = 0.0f, Z1 = 0.0f;
        int pos0 = -1, pos1 = -1;
#pragma unroll
        for (int k = 0; k < 32; k++) {
            const int a0 = (av[k] << 16) >> 16;
            const int a1 = av[k] >> 16;
            Z0 += table[a0 - amax0 + 128];
            Z1 += table[a1 - amax1 + 128];
            if (a0 == amax0) pos0 = lane + 32 * k;
            if (a1 == amax1) pos1 = lane + 32 * k;
        }
#pragma unroll
        for (int off = 16; off; off >>= 1) {
            Z0 += __shfl_xor_sync(0xffffffffu, Z0, off);
            Z1 += __shfl_xor_sync(0xffffffffu, Z1, off);
        }

        const unsigned bal0 = __ballot_sync(0xffffffffu, pos0 >= 0);
        const unsigned bal1 = __ballot_sync(0xffffffffu, pos1 >= 0);
        const int mpos0 = __shfl_sync(0xffffffffu, pos0, __ffs(bal0) - 1);
        const int mpos1 = __shfl_sync(0xffffffffu, pos1, __ffs(bal1) - 1);

        const float p0 = 1.0f / Z0;
        const float p1 = 1.0f / Z1;
        const bool s0 = (p0 + 0.5f) >= 1.0f;
        const bool s1 = (p1 + 0.5f) >= 1.0f;

        char2 o0 = make_char2(0, 0), o1 = make_char2(0, 0);
        if (s0) o0 = *(const char2*)(vbase + (size_t)mpos0 * 64 + 2 * lane);
        if (s1) o1 = *(const char2*)(vbase + (size_t)mpos1 * 64 + 2 * lane);
        if (s0 || s1) g_flag[bb * 8 + (r0 >> 7)] = 1;   // group = global row / 128
        *(char2*)(g_t + (size_t)(bb * 1024 + r0) * 768 + h * 64 + 2 * lane) = o0;
        *(char2*)(g_t + (size_t)(bb * 1024 + r1) * 768 + h * 64 + 2 * lane) = o1;
    }
}

// ---------------------------------------------------------------------------
// GEMM2: Out[m,o] = tern( sum_c T[m,c]*Wproj[o,c] )  (M=8192,N=768,K=768)
// Fast path: if this 128-row group had no attention spike, T rows are all zero
// -> output tile is exactly zero. Otherwise full fp32 path (bit-exact).
// ---------------------------------------------------------------------------
__global__ void __launch_bounds__(256, 2) gemm_proj_kernel(const float* __restrict__ W,
                                                           float* __restrict__ Out) {
    __shared__ float As[2][16][132];
    __shared__ float Bs[2][16][132];
    const int tid = threadIdx.x;
    const int tx = tid & 15, ty = tid >> 4;
    const int rowBase = blockIdx.y * 128;
    const int colBase = blockIdx.x * 128;

    if (g_flag[blockIdx.y] == 0) {
        // whole 128-row group is zero: tern(0)=0 exactly
        const float4 z = make_float4(0.f, 0.f, 0.f, 0.f);
#pragma unroll
        for (int i = 0; i < 8; i++) {
            float* op = Out + (size_t)(rowBase + ty * 8 + i) * 768 + colBase + tx * 8;
            *(float4*)op = z;
            *(float4*)(op + 4) = z;
        }
        return;
    }

    const int lr = tid >> 1;
    const int lk = (tid & 1) * 8;
    const float* Bg = W + (size_t)(colBase + lr) * 768 + lk;
    const signed char* Agc = g_t + (size_t)(rowBase + (tid & 127)) * 768;

    float acc[8][8];
#pragma unroll
    for (int i = 0; i < 8; i++)
#pragma unroll
        for (int j = 0; j < 8; j++) acc[i][j] = 0.0f;

    if (tid < 128) {
        const int4 raw = *(const int4*)(Agc);
        const signed char* cp = (const signed char*)&raw;
#pragma unroll
        for (int k2 = 0; k2 < 16; k2++) As[0][k2][tid] = (float)cp[k2];
    }
    {
        const float4 b0 = *(const float4*)Bg;
        const float4 b1 = *(const float4*)(Bg + 4);
        Bs[0][lk + 0][lr] = b0.x; Bs[0][lk + 1][lr] = b0.y;
        Bs[0][lk + 2][lr] = b0.z; Bs[0][lk + 3][lr] = b0.w;
        Bs[0][lk + 4][lr] = b1.x; Bs[0][lk + 5][lr] = b1.y;
        Bs[0][lk + 6][lr] = b1.z; Bs[0][lk + 7][lr] = b1.w;
    }
    __syncthreads();

    int buf = 0;
    for (int kt = 0; kt < 768; kt += 16) {
        int4 nraw; float4 nb0, nb1;
        const bool nxt = (kt + 16) < 768;
        if (nxt) {
            if (tid < 128) nraw = *(const int4*)(Agc + kt + 16);
            nb0 = *(const float4*)(Bg + kt + 16);
            nb1 = *(const float4*)(Bg + kt + 20);
        }
#pragma unroll
        for (int kk = 0; kk < 16; kk++) {
            float a[8], b[8];
            *(float4*)(a)     = *(const float4*)&As[buf][kk][ty * 8];
            *(float4*)(a + 4) = *(const float4*)&As[buf][kk][ty * 8 + 4];
            *(float4*)(b)     = *(const float4*)&Bs[buf][kk][tx * 8];
            *(float4*)(b + 4) = *(const float4*)&Bs[buf][kk][tx * 8 + 4];
#pragma unroll
            for (int i = 0; i < 8; i++)
#pragma unroll
                for (int j = 0; j < 8; j++) acc[i][j] = fmaf(a[i], b[j], acc[i][j]);
        }
        if (nxt) {
            const int nb2 = buf ^ 1;
            if (tid < 128) {
                const signed char* cp = (const signed char*)&nraw;
#pragma unroll
                for (int k2 = 0; k2 < 16; k2++) As[nb2][k2][tid] = (float)cp[k2];
            }
            Bs[nb2][lk + 0][lr] = nb0.x; Bs[nb2][lk + 1][lr] = nb0.y;
            Bs[nb2][lk + 2][lr] = nb0.z; Bs[nb2][lk + 3][lr] = nb0.w;
            Bs[nb2][lk + 4][lr] = nb1.x; Bs[nb2][lk + 5][lr] = nb1.y;
            Bs[nb2][lk + 6][lr] = nb1.z; Bs[nb2][lk + 7][lr] = nb1.w;
        }
        __syncthreads();
        buf ^= 1;
    }

#pragma unroll
    for (int i = 0; i < 8; i++) {
        const int row = rowBase + ty * 8 + i;
        float o[8];
#pragma unroll
        for (int j = 0; j < 8; j++) {
            const float u = acc[i][j] + 0.5f;
            o[j] = (u >= 1.0f) ? 1.0f : ((u < 0.0f) ? -1.0f : 0.0f);
        }
        float* op = Out + (size_t)row * 768 + colBase + tx * 8;
        *(float4*)op       = make_float4(o[0], o[1], o[2], o[3]);
        *(float4*)(op + 4) = make_float4(o[4], o[5], o[6], o[7]);
    }
}

// ---------------------------------------------------------------------------
extern "C" void kernel_launch(void* const* d_in, const int* in_sizes, int n_in,
                              void* d_out, int out_size) {
    (void)in_sizes; (void)n_in; (void)out_size;
    const float* x      = (const float*)d_in[0];
    const float* w_qkv  = (const float*)d_in[1];
    const float* w_proj = (const float*)d_in[2];
    float* out = (float*)d_out;

    cudaFuncSetAttribute(gemm_qkv_kernel, cudaFuncAttributeMaxDynamicSharedMemorySize, 50176);
    cudaFuncSetAttribute(attn_kernel, cudaFuncAttributeMaxDynamicSharedMemorySize, 66560);

    gemm_qkv_kernel<<<dim3(9, 64), 256, 50176>>>(x, w_qkv);   // N=2304/256, M=8192/128
    init_flags_kernel<<<1, 64>>>();
    attn_kernel<<<dim3(96, 16), 256, 66560>>>();
    gemm_proj_kernel<<<dim3(6, 64), 256>>>(w_proj, out);
}